// round 8
// baseline (speedup 1.0000x reference)
#include <cuda_runtime.h>
#include <cuda_bf16.h>
#include <math.h>
#include <stdint.h>

#define HCH 511
#define LSEQ 2048
#define NM 32
#define TCH 64          // chunk length
#define NCHKS 32        // chunks per sequence
#define KPAD 512
#define MPAD 1024
#define TWOH 1022

// ---------------- scratch (device globals) ----------------
__device__ float2 g_wC[HCH * NM];               // w^64 (double-computed)
__device__ float  g_KK[HCH * TCH];              // real kernel taps, d=0..63
__device__ float4 g_F[HCH * 32 * NM];           // [h][jp][n]: (Fr[2jp],Fi[2jp],Fr[2jp+1],Fi[2jp+1])
__device__ float2 g_G[HCH * NM * TCH];          // [h][n][j]: 2 c w^{j+1}
__device__ float  g_Y2p[3][TWOH * LSEQ];        // split-K partial GEMM outputs
__device__ float  g_Za[HCH * LSEQ];             // ping-pong activations
__device__ float  g_Zb[HCH * LSEQ];
__device__ __nv_bfloat16 g_Ahi[MPAD * KPAD];    // weight split, [m][k], zero padded
__device__ __nv_bfloat16 g_Alo[MPAD * KPAD];
__device__ __nv_bfloat16 g_Bhi[KPAD * LSEQ];    // activation split, K-major [k][n]
__device__ __nv_bfloat16 g_Blo[KPAD * LSEQ];

__device__ __forceinline__ const float* zsrc_ptr(int sel, const float* ext) {
    return sel < 0 ? ext : (sel == 0 ? g_Za : g_Zb);
}

// ---------------- prep: discretize + build KK/F/G tables (one warp per channel) --
__global__ __launch_bounds__(32) void kprep_kernel(const float* __restrict__ log_dt,
                                                   const float* __restrict__ Arl,
                                                   const float* __restrict__ Aim,
                                                   const float* __restrict__ Cre,
                                                   const float* __restrict__ Cim) {
    int h    = blockIdx.x;
    int lane = threadIdx.x;
    int idx  = h * NM + lane;
    float dt  = expf(log_dt[h]);
    float Ar  = -expf(Arl[idx]);
    float Ai  = Aim[idx];
    float dar = Ar * dt, dai = Ai * dt;
    float er  = expf(dar);
    float wr  = er * cosf(dai);
    float wi  = er * sinf(dai);
    // c2 = 2 * (Cre + i Cim) * (w - 1) / A
    float e1r = wr - 1.f, e1i = wi;
    float inv = 1.f / (Ar * Ar + Ai * Ai);
    float fr  = (e1r * Ar + e1i * Ai) * inv;
    float fi  = (e1i * Ar - e1r * Ai) * inv;
    float c2r = 2.f * (Cre[idx] * fr - Cim[idx] * fi);
    float c2i = 2.f * (Cre[idx] * fi + Cim[idx] * fr);
    // w^64 in double for the cross-chunk scan
    {
        double ph = (double)dai * (double)TCH;
        double sv, cv;
        sincos(ph, &sv, &cv);
        double eC = exp((double)dar * (double)TCH);
        g_wC[idx] = make_float2((float)(eC * cv), (float)(eC * sv));
    }
    // fp32 power recurrence: p = w^d
    float pr = 1.f, pi = 0.f;
    for (int d = 0; d <= TCH; d++) {
        if (d < TCH) {
            // KK[d] = sum_n Re(c2 * w^d)
            float kv = c2r * pr - c2i * pi;
            float s = kv;
            s += __shfl_xor_sync(0xffffffffu, s, 16);
            s += __shfl_xor_sync(0xffffffffu, s, 8);
            s += __shfl_xor_sync(0xffffffffu, s, 4);
            s += __shfl_xor_sync(0xffffffffu, s, 2);
            s += __shfl_xor_sync(0xffffffffu, s, 1);
            if (lane == 0) g_KK[h * TCH + d] = s;
            // F[j] = w^{63-j}  (stored at j = 63-d)
            int j = (TCH - 1) - d;
            float2* fdst = reinterpret_cast<float2*>(g_F) +
                           (((h * 32 + (j >> 1)) * NM + lane) * 2 + (j & 1));
            *fdst = make_float2(pr, pi);
        }
        if (d >= 1) {
            // G[n][d-1] = c2 * w^d
            g_G[(h * NM + lane) * TCH + (d - 1)] =
                make_float2(c2r * pr - c2i * pi, c2r * pi + c2i * pr);
        }
        float npr = fmaf(pr, wr, -pi * wi);
        float npi = fmaf(pr, wi,  pi * wr);
        pr = npr; pi = npi;
    }
}

// ---------------- prep: split glu_w into bf16 hi/lo; zero pad rows --------------
__global__ void asplit_kernel(const float* __restrict__ gw) {
    int idx = blockIdx.x * blockDim.x + threadIdx.x;   // 0 .. 1024*512-1
    int m = idx >> 9;
    int k = idx & 511;
    float v = (m < TWOH && k < HCH) ? gw[m * HCH + k] : 0.f;
    __nv_bfloat16 hi = __float2bfloat16(v);
    g_Ahi[idx] = hi;
    g_Alo[idx] = __float2bfloat16(v - __bfloat162float(hi));
    if (idx < LSEQ) {   // zero the k=511 pad row of B
        g_Bhi[HCH * LSEQ + idx] = __float2bfloat16(0.f);
        g_Blo[HCH * LSEQ + idx] = __float2bfloat16(0.f);
    }
}

// ---------------- conv: chunked tap-conv + state injection (no serial scan) ------
__global__ __launch_bounds__(512) void conv_kernel(const float* __restrict__ Zext,
                                                   const float* __restrict__ Dsk, int src) {
    __shared__ float  zs[LSEQ];
    __shared__ float  zpriv[16][2 * TCH];       // per-warp zero-padded window
    __shared__ float2 Sloc[NCHKS][NM];
    __shared__ float2 S0s[NCHKS][NM];
    __shared__ float  KKs[TCH];
    int h    = blockIdx.x;
    int tid  = threadIdx.x;
    int wid  = tid >> 5;
    int lane = tid & 31;
    const float* zrow = zsrc_ptr(src, Zext) + h * LSEQ;
    for (int i = tid; i < LSEQ; i += 512) zs[i] = zrow[i];
    if (tid < TCH) KKs[tid] = g_KK[h * TCH + tid];
    __syncthreads();

    // Pass A: per-chunk local state sums S_loc[n] = sum_j F[n][j] z[j]
    const float4* Fp = g_F + h * 32 * NM;
    #pragma unroll
    for (int cc = 0; cc < 2; cc++) {
        int c    = wid + cc * 16;
        int base = c * TCH;
        float sr0 = 0.f, si0 = 0.f, sr1 = 0.f, si1 = 0.f;
        #pragma unroll 8
        for (int jp = 0; jp < 32; jp += 2) {
            float4 f0 = Fp[jp * NM + lane];
            float2 z0 = *reinterpret_cast<const float2*>(&zs[base + jp * 2]);
            sr0 = fmaf(f0.x, z0.x, fmaf(f0.z, z0.y, sr0));
            si0 = fmaf(f0.y, z0.x, fmaf(f0.w, z0.y, si0));
            float4 f1 = Fp[(jp + 1) * NM + lane];
            float2 z1 = *reinterpret_cast<const float2*>(&zs[base + jp * 2 + 2]);
            sr1 = fmaf(f1.x, z1.x, fmaf(f1.z, z1.y, sr1));
            si1 = fmaf(f1.y, z1.x, fmaf(f1.w, z1.y, si1));
        }
        Sloc[c][lane] = make_float2(sr0 + sr1, si0 + si1);
    }
    __syncthreads();

    // cross-chunk scan (warp 0, lane = mode): S0[c+1] = w^64 S0[c] + Sloc[c]
    if (wid == 0) {
        float2 wc = g_wC[h * NM + lane];
        float cr = 0.f, ci = 0.f;
        #pragma unroll
        for (int c = 0; c < NCHKS; c++) {
            S0s[c][lane] = make_float2(cr, ci);
            float2 b = Sloc[c][lane];
            float nr = fmaf(wc.x, cr, fmaf(-wc.y, ci, b.x));
            float ni = fmaf(wc.y, cr, fmaf(wc.x, ci, b.y));
            cr = nr; ci = ni;
        }
    }
    __syncthreads();

    // Pass C: triangular tap-conv + injection; each lane emits 2 timesteps
    float Dh = Dsk[h];
    const float2* Gp = g_G + h * NM * TCH;
    __nv_bfloat16* bh = g_Bhi + h * LSEQ;
    __nv_bfloat16* bl = g_Blo + h * LSEQ;
    #pragma unroll
    for (int cc = 0; cc < 2; cc++) {
        int c    = wid + cc * 16;
        int base = c * TCH;
        // fill zero-padded private window
        #pragma unroll
        for (int q = 0; q < 4; q++) {
            int idx = lane * 4 + q;                 // 0..127
            zpriv[wid][idx] = (idx < TCH) ? 0.f : zs[base + idx - TCH];
        }
        __syncwarp();

        float y0 = 0.f, y1 = 0.f;
        const float* zp = &zpriv[wid][TCH + lane * 2];   // z[j0], j0 = 2*lane
        #pragma unroll 8
        for (int dp = 0; dp < 32; dp++) {
            int d0 = dp * 2;
            float2 kk = *reinterpret_cast<const float2*>(&KKs[d0]);
            float2 za = *reinterpret_cast<const float2*>(zp - d0);       // z[j0-d0], z[j1-d0]
            float2 zb = *reinterpret_cast<const float2*>(zp - d0 - 2);   // _, z[j0-d0-1]
            y0 = fmaf(kk.x, za.x, y0);
            y1 = fmaf(kk.x, za.y, y1);
            y0 = fmaf(kk.y, zb.y, y0);
            y1 = fmaf(kk.y, za.x, y1);
        }
        // injection: y[j] += Gr[n][j] S0r[n] - Gi[n][j] S0i[n]
        #pragma unroll 4
        for (int n = 0; n < NM; n++) {
            float4 g4 = *reinterpret_cast<const float4*>(&Gp[n * TCH + lane * 2]);
            float2 s0 = S0s[c][n];
            y0 = fmaf(g4.x, s0.x, fmaf(-g4.y, s0.y, y0));
            y1 = fmaf(g4.z, s0.x, fmaf(-g4.w, s0.y, y1));
        }
        // epilogue: +D*z, gelu, bf16 hi/lo split write (2 adjacent timesteps)
        int l0 = base + lane * 2;
        float z0 = zs[l0], z1 = zs[l0 + 1];
        float x0 = fmaf(Dh, z0, y0);
        float x1 = fmaf(Dh, z1, y1);
        float t0 = tanhf(0.7978845608028654f * fmaf(0.044715f, x0 * x0 * x0, x0));
        float t1 = tanhf(0.7978845608028654f * fmaf(0.044715f, x1 * x1 * x1, x1));
        float gl0 = 0.5f * x0 * (1.f + t0);
        float gl1 = 0.5f * x1 * (1.f + t1);
        __nv_bfloat16 h0 = __float2bfloat16(gl0);
        __nv_bfloat16 h1 = __float2bfloat16(gl1);
        __nv_bfloat162 hv; hv.x = h0; hv.y = h1;
        __nv_bfloat162 lv;
        lv.x = __float2bfloat16(gl0 - __bfloat162float(h0));
        lv.y = __float2bfloat16(gl1 - __bfloat162float(h1));
        *reinterpret_cast<__nv_bfloat162*>(&bh[l0]) = hv;
        *reinterpret_cast<__nv_bfloat162*>(&bl[l0]) = lv;
        __syncwarp();
    }
}

// ---------------- HMMA GEMM, split-K x3: P[seg] = Aseg @ Bseg ---------------------
__device__ __forceinline__ void cp16(uint32_t saddr, const void* gptr) {
    asm volatile("cp.async.ca.shared.global [%0], [%1], 16;" :: "r"(saddr), "l"(gptr));
}
__device__ __forceinline__ uint32_t swzA(int row, int ch) {
    return (uint32_t)(row * 64 + ((ch ^ ((row >> 1) & 3)) << 4));
}
__device__ __forceinline__ uint32_t swzB(int row, int ch) {
    return (uint32_t)(row * 256 + ((ch ^ (row & 7)) << 4));
}

__global__ __launch_bounds__(256, 2) void gemm_hmma_kernel() {
    __shared__ __align__(128) char sA[3][8192];
    __shared__ __align__(128) char sB[3][8192];

    const int t    = threadIdx.x;
    const int wid  = t >> 5;
    const int lane = t & 31;
    const int n0   = blockIdx.x * 128;
    const int m0   = blockIdx.y * 128;
    const int seg  = blockIdx.z;
    const int wm   = (wid & 1) * 64;
    const int wn   = (wid >> 1) * 32;

    const __nv_bfloat16* Ap = (seg == 2) ? g_Alo : g_Ahi;
    const __nv_bfloat16* Bp = (seg == 1) ? g_Blo : g_Bhi;

    const uint32_t sAu = (uint32_t)__cvta_generic_to_shared(&sA[0][0]);
    const uint32_t sBu = (uint32_t)__cvta_generic_to_shared(&sB[0][0]);

    const int arow0 = t >> 2, ach = t & 3;
    const int arow1 = arow0 + 64;
    const uint32_t aso0 = swzA(arow0, ach);
    const uint32_t aso1 = swzA(arow1, ach);
    const int brow0 = t >> 4,         bch0 = t & 15;
    const int brow1 = (t + 256) >> 4, bch1 = t & 15;
    const uint32_t bso0 = swzB(brow0, bch0);
    const uint32_t bso1 = swzB(brow1, bch1);

    const int ra = lane & 15;
    const int ca = lane >> 4;
    const int bg = lane >> 3;
    const int br = lane & 7;

    float acc[4][4][4];
    #pragma unroll
    for (int i = 0; i < 4; i++)
        #pragma unroll
        for (int j = 0; j < 4; j++)
            #pragma unroll
            for (int q = 0; q < 4; q++) acc[i][j][q] = 0.f;

    #pragma unroll
    for (int st = 0; st < 2; st++) {
        const uint32_t dA = sAu + st * 8192;
        const uint32_t dB = sBu + st * 8192;
        cp16(dA + aso0, Ap + (m0 + arow0) * KPAD + st * 32 + ach * 8);
        cp16(dA + aso1, Ap + (m0 + arow1) * KPAD + st * 32 + ach * 8);
        cp16(dB + bso0, Bp + (st * 32 + brow0) * LSEQ + n0 + bch0 * 8);
        cp16(dB + bso1, Bp + (st * 32 + brow1) * LSEQ + n0 + bch1 * 8);
        asm volatile("cp.async.commit_group;" ::: "memory");
    }

    for (int it = 0; it < 16; it++) {
        const int buf = it % 3;
        const uint32_t sAb = sAu + buf * 8192;
        const uint32_t sBb = sBu + buf * 8192;

        asm volatile("cp.async.wait_group 1;" ::: "memory");
        __syncthreads();

        #pragma unroll
        for (int ks = 0; ks < 2; ks++) {
            uint32_t a[4][4], b[4][2];
            #pragma unroll
            for (int mt = 0; mt < 4; mt++) {
                uint32_t ad = sAb + swzA(wm + mt * 16 + ra, ks * 2 + ca);
                asm volatile("ldmatrix.sync.aligned.m8n8.x4.shared.b16 {%0,%1,%2,%3}, [%4];"
                             : "=r"(a[mt][0]), "=r"(a[mt][1]), "=r"(a[mt][2]), "=r"(a[mt][3])
                             : "r"(ad));
            }
            #pragma unroll
            for (int nh = 0; nh < 2; nh++) {
                int krow = ks * 16 + (bg & 1) * 8 + br;
                int nch  = (wn >> 3) + nh * 2 + (bg >> 1);
                uint32_t bd = sBb + swzB(krow, nch);
                uint32_t r0, r1, r2, r3;
                asm volatile("ldmatrix.sync.aligned.m8n8.x4.trans.shared.b16 {%0,%1,%2,%3}, [%4];"
                             : "=r"(r0), "=r"(r1), "=r"(r2), "=r"(r3) : "r"(bd));
                b[nh * 2][0] = r0;     b[nh * 2][1] = r1;
                b[nh * 2 + 1][0] = r2; b[nh * 2 + 1][1] = r3;
            }
            #pragma unroll
            for (int mt = 0; mt < 4; mt++)
                #pragma unroll
                for (int nt = 0; nt < 4; nt++) {
                    asm volatile(
                        "mma.sync.aligned.m16n8k16.row.col.f32.bf16.bf16.f32 "
                        "{%0,%1,%2,%3}, {%4,%5,%6,%7}, {%8,%9}, {%0,%1,%2,%3};"
                        : "+f"(acc[mt][nt][0]), "+f"(acc[mt][nt][1]),
                          "+f"(acc[mt][nt][2]), "+f"(acc[mt][nt][3])
                        : "r"(a[mt][0]), "r"(a[mt][1]), "r"(a[mt][2]), "r"(a[mt][3]),
                          "r"(b[nt][0]), "r"(b[nt][1]));
                }
        }

        if (it + 2 < 16) {
            const int kc = it + 2;
            const uint32_t dA = sAu + (kc % 3) * 8192;
            const uint32_t dB = sBu + (kc % 3) * 8192;
            cp16(dA + aso0, Ap + (m0 + arow0) * KPAD + kc * 32 + ach * 8);
            cp16(dA + aso1, Ap + (m0 + arow1) * KPAD + kc * 32 + ach * 8);
            cp16(dB + bso0, Bp + (kc * 32 + brow0) * LSEQ + n0 + bch0 * 8);
            cp16(dB + bso1, Bp + (kc * 32 + brow1) * LSEQ + n0 + bch1 * 8);
        }
        asm volatile("cp.async.commit_group;" ::: "memory");
    }

    float* outp = g_Y2p[seg];
    #pragma unroll
    for (int mt = 0; mt < 4; mt++) {
        int mr0 = m0 + wm + mt * 16 + (lane >> 2);
        #pragma unroll
        for (int nt = 0; nt < 4; nt++) {
            int nc = n0 + wn + nt * 8 + (lane & 3) * 2;
            if (mr0 < TWOH)
                *reinterpret_cast<float2*>(&outp[mr0 * LSEQ + nc]) =
                    make_float2(acc[mt][nt][0], acc[mt][nt][1]);
            if (mr0 + 8 < TWOH)
                *reinterpret_cast<float2*>(&outp[(mr0 + 8) * LSEQ + nc]) =
                    make_float2(acc[mt][nt][2], acc[mt][nt][3]);
        }
    }
}

// ---------------- GLU + bias + residual + channel LayerNorm (smem-cached) --------
__global__ __launch_bounds__(512) void lnglu_kernel(const float* __restrict__ Zext,
                                                    const float* __restrict__ gb,
                                                    const float* __restrict__ lng,
                                                    const float* __restrict__ lnb,
                                                    float* __restrict__ ext_out,
                                                    int src, int dst) {
    __shared__ float gsm[HCH * 16];
    __shared__ float r1[32][17], r2[32][17];
    __shared__ float mu_s[16], rs_s[16];

    const float* res = zsrc_ptr(src, Zext);
    float* outp = dst < 0 ? ext_out : (dst == 0 ? g_Za : g_Zb);
    const float* P0 = g_Y2p[0];
    const float* P1 = g_Y2p[1];
    const float* P2 = g_Y2p[2];
    int tx = threadIdx.x & 15;
    int hg = threadIdx.x >> 4;
    int l  = blockIdx.x * 16 + tx;

    float s1 = 0.f, s2 = 0.f;
    for (int h = hg; h < HCH; h += 32) {
        int ia = h * LSEQ + l;
        int ib = (h + HCH) * LSEQ + l;
        float a = (P0[ia] + P1[ia]) + P2[ia] + gb[h];
        float b = (P0[ib] + P1[ib]) + P2[ib] + gb[h + HCH];
        float g = a / (1.f + __expf(-b)) + res[ia];
        gsm[h * 16 + tx] = g;
        s1 += g; s2 += g * g;
    }
    r1[hg][tx] = s1; r2[hg][tx] = s2;
    __syncthreads();
    if (threadIdx.x < 16) {
        float a1 = 0.f, a2 = 0.f;
        #pragma unroll
        for (int j = 0; j < 32; j++) { a1 += r1[j][threadIdx.x]; a2 += r2[j][threadIdx.x]; }
        float mu  = a1 * (1.f / (float)HCH);
        float var = a2 * (1.f / (float)HCH) - mu * mu;
        mu_s[threadIdx.x] = mu;
        rs_s[threadIdx.x] = rsqrtf(var + 1e-5f);
    }
    __syncthreads();
    float mu = mu_s[tx], rs = rs_s[tx];
    for (int h = hg; h < HCH; h += 32) {
        float g = gsm[h * 16 + tx];
        outp[h * LSEQ + l] = (g - mu) * rs * lng[h] + lnb[h];
    }
}

// ---------------- launch ----------------
extern "C" void kernel_launch(void* const* d_in, const int* in_sizes, int n_in,
                              void* d_out, int out_size) {
    const float* Z      = (const float*)d_in[0];
    const float* log_dt = (const float*)d_in[1];
    const float* Arl    = (const float*)d_in[2];
    const float* Aim    = (const float*)d_in[3];
    const float* Cre    = (const float*)d_in[4];
    const float* Cim    = (const float*)d_in[5];
    const float* Dsk    = (const float*)d_in[6];
    const float* gw     = (const float*)d_in[7];
    const float* gb     = (const float*)d_in[8];
    const float* lng    = (const float*)d_in[9];
    const float* lnb    = (const float*)d_in[10];
    float* out = (float*)d_out;

    kprep_kernel<<<HCH, 32>>>(log_dt, Arl, Aim, Cre, Cim);
    asplit_kernel<<<(MPAD * KPAD) / 256, 256>>>(gw);

    const int srcs[4] = {-1, 0, 1, 0};
    const int dsts[4] = { 0, 1, 0, -1};
    for (int layer = 0; layer < 4; ++layer) {
        conv_kernel<<<HCH, 512>>>(Z, Dsk, srcs[layer]);
        gemm_hmma_kernel<<<dim3(16, 8, 3), 256>>>();
        lnglu_kernel<<<128, 512>>>(Z, gb, lng, lnb, out, srcs[layer], dsts[layer]);
    }
}